// round 8
// baseline (speedup 1.0000x reference)
#include <cuda_runtime.h>
#include <cstddef>

// ---------------------------------------------------------------------------
// RBFolution: out[b,oh,ow,f] = exp(-beta[f] * (||p||^2 - 2 p.ccs[:,f] + ||c_f||^2))
// B=32,H=W=112,C=32,F=128,D=288, valid 3x3 -> Ho=Wo=110.
//
// R7: occupancy fix. F-split: each block handles 64 of the 128 filters, so
// smem drops to ~96 KB and 2 blocks/SM co-reside (16 warps, 4/SMSP) to hide
// LDS latency. A-loads vectorized (float4 over C) to cut LDS issue count.
//
// Block: 256 threads, tile 16x8 pixels x 64 filters.
//   fid  = tid & 7        -> filters fid*4..+3 and fid*4+32..+3 (within half)
//   prow = (tid>>3) & 15  -> pixel row in tile
//   pcg  = tid >> 7       -> pixel column group (4 cols each)
// Per thread: 4 px x 8 filters = 32 accumulators.
// ---------------------------------------------------------------------------

#define Bn 32
#define Hn 112
#define Wn 112
#define Cn 32
#define Fn 128
#define FHALF 64
#define HoN 110
#define WoN 110
#define Dn 288            // 3*3*Cn

#define TILE_H 16
#define TILE_W 8
#define THREADS 256

#define XS_H (TILE_H + 2)         // 18
#define XS_W (TILE_W + 2)         // 10
#define XS_RPITCH (XS_W * Cn + 4) // 324 floats: row stride = 4 banks -> A loads conflict-free

#define SMEM_FLOATS (Dn * FHALF + XS_H * XS_RPITCH + TILE_H * TILE_W + FHALF + FHALF)
#define SMEM_BYTES (SMEM_FLOATS * 4)

__global__ void __launch_bounds__(THREADS, 2)
rbfolution_kernel(const float* __restrict__ x,
                  const float* __restrict__ ccs,
                  const float* __restrict__ beta,
                  float* __restrict__ out)
{
    extern __shared__ float smem[];
    float* sccs  = smem;                         // [Dn][FHALF]   73728 B
    float* xs    = sccs + Dn * FHALF;            // [XS_H][XS_RPITCH]  23328 B
    float* psq   = xs + XS_H * XS_RPITCH;        // [128] per-pixel ||p||^2
    float* csq   = psq + TILE_H * TILE_W;        // [64] per-filter ||c||^2
    float* sbeta = csq + FHALF;                  // [64]

    const int tid = threadIdx.x;
    const int bz  = blockIdx.z;
    const int b   = bz >> 1;
    const int fh  = bz & 1;                      // filter half: 0 or 1
    const int oh0 = blockIdx.y * TILE_H;
    const int ow0 = blockIdx.x * TILE_W;

    // ---- load this block's 64-filter slice of ccs into smem ----
    // global ccs is [Dn][Fn]; we want columns [fh*64, fh*64+64).
    {
        const float4* src = reinterpret_cast<const float4*>(ccs);
        float4* dst = reinterpret_cast<float4*>(sccs);
        const int fh16 = fh * (FHALF / 4);       // float4 col offset within a d-row
        #pragma unroll
        for (int it = 0; it < (Dn * FHALF / 4) / THREADS; ++it) {  // 18 iters
            int i = tid + it * THREADS;
            int d = i >> 4;                      // / (FHALF/4)
            int v = i & 15;
            dst[i] = src[d * (Fn / 4) + fh16 + v];
        }
    }

    // ---- load x halo tile (18 x 10 x 32), zero-fill out-of-bounds ----
    {
        const int NV = XS_H * XS_W * (Cn / 4);   // 1440 float4 slots (logical)
        for (int i = tid; i < NV; i += THREADS) {
            int pos = i / (Cn / 4);
            int v   = i % (Cn / 4);
            int r   = pos / XS_W;
            int col = pos % XS_W;
            int gr  = oh0 + r;
            int gc  = ow0 + col;
            float4 val = make_float4(0.f, 0.f, 0.f, 0.f);
            if (gr < Hn && gc < Wn) {
                val = *reinterpret_cast<const float4*>(
                    x + (((size_t)b * Hn + gr) * Wn + gc) * Cn + v * 4);
            }
            float* d = xs + r * XS_RPITCH + col * Cn + v * 4;
            d[0] = val.x; d[1] = val.y; d[2] = val.z; d[3] = val.w;
        }
    }
    __syncthreads();

    // ---- threads 0-127: per-pixel ||p||^2 ; threads 128-191: ||c||^2 + beta ----
    if (tid < TILE_H * TILE_W) {
        const int ty = tid >> 3;   // 0..15
        const int tx = tid & 7;    // 0..7
        float s = 0.f;
        #pragma unroll
        for (int tr = 0; tr < 3; ++tr) {
            #pragma unroll
            for (int tc = 0; tc < 3; ++tc) {
                const float* p = xs + (ty + tr) * XS_RPITCH + (tx + tc) * Cn;
                #pragma unroll
                for (int c = 0; c < Cn; ++c) {
                    float v = p[c];
                    s = fmaf(v, v, s);
                }
            }
        }
        psq[tid] = s;
    } else if (tid < 128 + FHALF) {
        const int f = tid - 128;
        float s = 0.f;
        #pragma unroll 8
        for (int d = 0; d < Dn; ++d) {
            float v = sccs[d * FHALF + f];
            s = fmaf(v, v, s);
        }
        csq[f] = s;
        sbeta[f] = beta[fh * FHALF + f];
    }
    __syncthreads();

    // ---- main loop: acc[px][j] = dot(p, ccs[:, f]) over D ----
    const int fid  = tid & 7;          // filter group (8 groups x 8 filters)
    const int prow = (tid >> 3) & 15;  // pixel row within tile
    const int pcg  = tid >> 7;         // pixel column group (0 or 1)

    float acc[4][8];
    #pragma unroll
    for (int i = 0; i < 4; ++i)
        #pragma unroll
        for (int j = 0; j < 8; ++j)
            acc[i][j] = 0.f;

    #pragma unroll 1
    for (int tr = 0; tr < 3; ++tr) {
        #pragma unroll 1
        for (int tc = 0; tc < 3; ++tc) {
            const float* ap = xs + (prow + tr) * XS_RPITCH + (pcg * 4 + tc) * Cn;
            const float* bp = sccs + (size_t)(tr * 3 + tc) * Cn * FHALF + fid * 4;
            #pragma unroll 4
            for (int c4 = 0; c4 < Cn / 4; ++c4) {
                // A: 4 pixels x 4 channels (vectorized over C)
                float a0[4], a1[4], a2[4], a3[4];
                *reinterpret_cast<float4*>(a0) =
                    *reinterpret_cast<const float4*>(ap + 0 * Cn + c4 * 4);
                *reinterpret_cast<float4*>(a1) =
                    *reinterpret_cast<const float4*>(ap + 1 * Cn + c4 * 4);
                *reinterpret_cast<float4*>(a2) =
                    *reinterpret_cast<const float4*>(ap + 2 * Cn + c4 * 4);
                *reinterpret_cast<float4*>(a3) =
                    *reinterpret_cast<const float4*>(ap + 3 * Cn + c4 * 4);
                #pragma unroll
                for (int cc = 0; cc < 4; ++cc) {
                    const float* brow = bp + (c4 * 4 + cc) * FHALF;
                    const float4 b0 = *reinterpret_cast<const float4*>(brow);
                    const float4 b1 = *reinterpret_cast<const float4*>(brow + 32);
                    acc[0][0] = fmaf(a0[cc], b0.x, acc[0][0]);
                    acc[0][1] = fmaf(a0[cc], b0.y, acc[0][1]);
                    acc[0][2] = fmaf(a0[cc], b0.z, acc[0][2]);
                    acc[0][3] = fmaf(a0[cc], b0.w, acc[0][3]);
                    acc[0][4] = fmaf(a0[cc], b1.x, acc[0][4]);
                    acc[0][5] = fmaf(a0[cc], b1.y, acc[0][5]);
                    acc[0][6] = fmaf(a0[cc], b1.z, acc[0][6]);
                    acc[0][7] = fmaf(a0[cc], b1.w, acc[0][7]);
                    acc[1][0] = fmaf(a1[cc], b0.x, acc[1][0]);
                    acc[1][1] = fmaf(a1[cc], b0.y, acc[1][1]);
                    acc[1][2] = fmaf(a1[cc], b0.z, acc[1][2]);
                    acc[1][3] = fmaf(a1[cc], b0.w, acc[1][3]);
                    acc[1][4] = fmaf(a1[cc], b1.x, acc[1][4]);
                    acc[1][5] = fmaf(a1[cc], b1.y, acc[1][5]);
                    acc[1][6] = fmaf(a1[cc], b1.z, acc[1][6]);
                    acc[1][7] = fmaf(a1[cc], b1.w, acc[1][7]);
                    acc[2][0] = fmaf(a2[cc], b0.x, acc[2][0]);
                    acc[2][1] = fmaf(a2[cc], b0.y, acc[2][1]);
                    acc[2][2] = fmaf(a2[cc], b0.z, acc[2][2]);
                    acc[2][3] = fmaf(a2[cc], b0.w, acc[2][3]);
                    acc[2][4] = fmaf(a2[cc], b1.x, acc[2][4]);
                    acc[2][5] = fmaf(a2[cc], b1.y, acc[2][5]);
                    acc[2][6] = fmaf(a2[cc], b1.z, acc[2][6]);
                    acc[2][7] = fmaf(a2[cc], b1.w, acc[2][7]);
                    acc[3][0] = fmaf(a3[cc], b0.x, acc[3][0]);
                    acc[3][1] = fmaf(a3[cc], b0.y, acc[3][1]);
                    acc[3][2] = fmaf(a3[cc], b0.z, acc[3][2]);
                    acc[3][3] = fmaf(a3[cc], b0.w, acc[3][3]);
                    acc[3][4] = fmaf(a3[cc], b1.x, acc[3][4]);
                    acc[3][5] = fmaf(a3[cc], b1.y, acc[3][5]);
                    acc[3][6] = fmaf(a3[cc], b1.z, acc[3][6]);
                    acc[3][7] = fmaf(a3[cc], b1.w, acc[3][7]);
                }
            }
        }
    }

    // ---- epilogue: score = psq + csq - 2*dot ; out = exp(-beta*score) ----
    const int oh = oh0 + prow;
    if (oh < HoN) {
        const int f0 = fid * 4;
        const float cs0 = csq[f0 + 0],  cs1 = csq[f0 + 1];
        const float cs2 = csq[f0 + 2],  cs3 = csq[f0 + 3];
        const float cs4 = csq[f0 + 32], cs5 = csq[f0 + 33];
        const float cs6 = csq[f0 + 34], cs7 = csq[f0 + 35];
        const float bt0 = sbeta[f0 + 0],  bt1 = sbeta[f0 + 1];
        const float bt2 = sbeta[f0 + 2],  bt3 = sbeta[f0 + 3];
        const float bt4 = sbeta[f0 + 32], bt5 = sbeta[f0 + 33];
        const float bt6 = sbeta[f0 + 34], bt7 = sbeta[f0 + 35];

        #pragma unroll
        for (int px = 0; px < 4; ++px) {
            const int ow = ow0 + pcg * 4 + px;
            if (ow < WoN) {
                const float ps = psq[prow * TILE_W + pcg * 4 + px];
                float4 r0, r1;
                r0.x = __expf(-bt0 * (ps + cs0 - 2.f * acc[px][0]));
                r0.y = __expf(-bt1 * (ps + cs1 - 2.f * acc[px][1]));
                r0.z = __expf(-bt2 * (ps + cs2 - 2.f * acc[px][2]));
                r0.w = __expf(-bt3 * (ps + cs3 - 2.f * acc[px][3]));
                r1.x = __expf(-bt4 * (ps + cs4 - 2.f * acc[px][4]));
                r1.y = __expf(-bt5 * (ps + cs5 - 2.f * acc[px][5]));
                r1.z = __expf(-bt6 * (ps + cs6 - 2.f * acc[px][6]));
                r1.w = __expf(-bt7 * (ps + cs7 - 2.f * acc[px][7]));
                float* op = out + (((size_t)b * HoN + oh) * WoN + ow) * Fn
                                + fh * FHALF + f0;
                *reinterpret_cast<float4*>(op)      = r0;
                *reinterpret_cast<float4*>(op + 32) = r1;
            }
        }
    }
}

extern "C" void kernel_launch(void* const* d_in, const int* in_sizes, int n_in,
                              void* d_out, int out_size)
{
    (void)in_sizes; (void)n_in; (void)out_size;
    const float* x    = (const float*)d_in[0];
    const float* ccs  = (const float*)d_in[1];
    const float* beta = (const float*)d_in[2];
    float* out = (float*)d_out;

    // Opt-in to >48KB dynamic smem (idempotent, not a stream op -> capture-safe).
    cudaFuncSetAttribute(rbfolution_kernel,
                         cudaFuncAttributeMaxDynamicSharedMemorySize, SMEM_BYTES);

    dim3 grid((WoN + TILE_W - 1) / TILE_W,   // 14
              (HoN + TILE_H - 1) / TILE_H,   // 7
              Bn * 2);                       // 32 batches x 2 filter halves
    rbfolution_kernel<<<grid, THREADS, SMEM_BYTES>>>(x, ccs, beta, out);
}

// round 9
// speedup vs baseline: 1.0001x; 1.0001x over previous
#include <cuda_runtime.h>
#include <cstddef>

// ---------------------------------------------------------------------------
// RBFolution: out[b,oh,ow,f] = exp(-beta[f] * (||p||^2 - 2 p.ccs[:,f] + ||c_f||^2))
// B=32,H=W=112,C=32,F=128,D=288, valid 3x3 -> Ho=Wo=110.
//
// R7: occupancy fix. F-split: each block handles 64 of the 128 filters, so
// smem drops to ~96 KB and 2 blocks/SM co-reside (16 warps, 4/SMSP) to hide
// LDS latency. A-loads vectorized (float4 over C) to cut LDS issue count.
//
// Block: 256 threads, tile 16x8 pixels x 64 filters.
//   fid  = tid & 7        -> filters fid*4..+3 and fid*4+32..+3 (within half)
//   prow = (tid>>3) & 15  -> pixel row in tile
//   pcg  = tid >> 7       -> pixel column group (4 cols each)
// Per thread: 4 px x 8 filters = 32 accumulators.
// ---------------------------------------------------------------------------

#define Bn 32
#define Hn 112
#define Wn 112
#define Cn 32
#define Fn 128
#define FHALF 64
#define HoN 110
#define WoN 110
#define Dn 288            // 3*3*Cn

#define TILE_H 16
#define TILE_W 8
#define THREADS 256

#define XS_H (TILE_H + 2)         // 18
#define XS_W (TILE_W + 2)         // 10
#define XS_RPITCH (XS_W * Cn + 4) // 324 floats: row stride = 4 banks -> A loads conflict-free

#define SMEM_FLOATS (Dn * FHALF + XS_H * XS_RPITCH + TILE_H * TILE_W + FHALF + FHALF)
#define SMEM_BYTES (SMEM_FLOATS * 4)

__global__ void __launch_bounds__(THREADS, 2)
rbfolution_kernel(const float* __restrict__ x,
                  const float* __restrict__ ccs,
                  const float* __restrict__ beta,
                  float* __restrict__ out)
{
    extern __shared__ float smem[];
    float* sccs  = smem;                         // [Dn][FHALF]   73728 B
    float* xs    = sccs + Dn * FHALF;            // [XS_H][XS_RPITCH]  23328 B
    float* psq   = xs + XS_H * XS_RPITCH;        // [128] per-pixel ||p||^2
    float* csq   = psq + TILE_H * TILE_W;        // [64] per-filter ||c||^2
    float* sbeta = csq + FHALF;                  // [64]

    const int tid = threadIdx.x;
    const int bz  = blockIdx.z;
    const int b   = bz >> 1;
    const int fh  = bz & 1;                      // filter half: 0 or 1
    const int oh0 = blockIdx.y * TILE_H;
    const int ow0 = blockIdx.x * TILE_W;

    // ---- load this block's 64-filter slice of ccs into smem ----
    // global ccs is [Dn][Fn]; we want columns [fh*64, fh*64+64).
    {
        const float4* src = reinterpret_cast<const float4*>(ccs);
        float4* dst = reinterpret_cast<float4*>(sccs);
        const int fh16 = fh * (FHALF / 4);       // float4 col offset within a d-row
        #pragma unroll
        for (int it = 0; it < (Dn * FHALF / 4) / THREADS; ++it) {  // 18 iters
            int i = tid + it * THREADS;
            int d = i >> 4;                      // / (FHALF/4)
            int v = i & 15;
            dst[i] = src[d * (Fn / 4) + fh16 + v];
        }
    }

    // ---- load x halo tile (18 x 10 x 32), zero-fill out-of-bounds ----
    {
        const int NV = XS_H * XS_W * (Cn / 4);   // 1440 float4 slots (logical)
        for (int i = tid; i < NV; i += THREADS) {
            int pos = i / (Cn / 4);
            int v   = i % (Cn / 4);
            int r   = pos / XS_W;
            int col = pos % XS_W;
            int gr  = oh0 + r;
            int gc  = ow0 + col;
            float4 val = make_float4(0.f, 0.f, 0.f, 0.f);
            if (gr < Hn && gc < Wn) {
                val = *reinterpret_cast<const float4*>(
                    x + (((size_t)b * Hn + gr) * Wn + gc) * Cn + v * 4);
            }
            float* d = xs + r * XS_RPITCH + col * Cn + v * 4;
            d[0] = val.x; d[1] = val.y; d[2] = val.z; d[3] = val.w;
        }
    }
    __syncthreads();

    // ---- threads 0-127: per-pixel ||p||^2 ; threads 128-191: ||c||^2 + beta ----
    if (tid < TILE_H * TILE_W) {
        const int ty = tid >> 3;   // 0..15
        const int tx = tid & 7;    // 0..7
        float s = 0.f;
        #pragma unroll
        for (int tr = 0; tr < 3; ++tr) {
            #pragma unroll
            for (int tc = 0; tc < 3; ++tc) {
                const float* p = xs + (ty + tr) * XS_RPITCH + (tx + tc) * Cn;
                #pragma unroll
                for (int c = 0; c < Cn; ++c) {
                    float v = p[c];
                    s = fmaf(v, v, s);
                }
            }
        }
        psq[tid] = s;
    } else if (tid < 128 + FHALF) {
        const int f = tid - 128;
        float s = 0.f;
        #pragma unroll 8
        for (int d = 0; d < Dn; ++d) {
            float v = sccs[d * FHALF + f];
            s = fmaf(v, v, s);
        }
        csq[f] = s;
        sbeta[f] = beta[fh * FHALF + f];
    }
    __syncthreads();

    // ---- main loop: acc[px][j] = dot(p, ccs[:, f]) over D ----
    const int fid  = tid & 7;          // filter group (8 groups x 8 filters)
    const int prow = (tid >> 3) & 15;  // pixel row within tile
    const int pcg  = tid >> 7;         // pixel column group (0 or 1)

    float acc[4][8];
    #pragma unroll
    for (int i = 0; i < 4; ++i)
        #pragma unroll
        for (int j = 0; j < 8; ++j)
            acc[i][j] = 0.f;

    #pragma unroll 1
    for (int tr = 0; tr < 3; ++tr) {
        #pragma unroll 1
        for (int tc = 0; tc < 3; ++tc) {
            const float* ap = xs + (prow + tr) * XS_RPITCH + (pcg * 4 + tc) * Cn;
            const float* bp = sccs + (size_t)(tr * 3 + tc) * Cn * FHALF + fid * 4;
            #pragma unroll 4
            for (int c4 = 0; c4 < Cn / 4; ++c4) {
                // A: 4 pixels x 4 channels (vectorized over C)
                float a0[4], a1[4], a2[4], a3[4];
                *reinterpret_cast<float4*>(a0) =
                    *reinterpret_cast<const float4*>(ap + 0 * Cn + c4 * 4);
                *reinterpret_cast<float4*>(a1) =
                    *reinterpret_cast<const float4*>(ap + 1 * Cn + c4 * 4);
                *reinterpret_cast<float4*>(a2) =
                    *reinterpret_cast<const float4*>(ap + 2 * Cn + c4 * 4);
                *reinterpret_cast<float4*>(a3) =
                    *reinterpret_cast<const float4*>(ap + 3 * Cn + c4 * 4);
                #pragma unroll
                for (int cc = 0; cc < 4; ++cc) {
                    const float* brow = bp + (c4 * 4 + cc) * FHALF;
                    const float4 b0 = *reinterpret_cast<const float4*>(brow);
                    const float4 b1 = *reinterpret_cast<const float4*>(brow + 32);
                    acc[0][0] = fmaf(a0[cc], b0.x, acc[0][0]);
                    acc[0][1] = fmaf(a0[cc], b0.y, acc[0][1]);
                    acc[0][2] = fmaf(a0[cc], b0.z, acc[0][2]);
                    acc[0][3] = fmaf(a0[cc], b0.w, acc[0][3]);
                    acc[0][4] = fmaf(a0[cc], b1.x, acc[0][4]);
                    acc[0][5] = fmaf(a0[cc], b1.y, acc[0][5]);
                    acc[0][6] = fmaf(a0[cc], b1.z, acc[0][6]);
                    acc[0][7] = fmaf(a0[cc], b1.w, acc[0][7]);
                    acc[1][0] = fmaf(a1[cc], b0.x, acc[1][0]);
                    acc[1][1] = fmaf(a1[cc], b0.y, acc[1][1]);
                    acc[1][2] = fmaf(a1[cc], b0.z, acc[1][2]);
                    acc[1][3] = fmaf(a1[cc], b0.w, acc[1][3]);
                    acc[1][4] = fmaf(a1[cc], b1.x, acc[1][4]);
                    acc[1][5] = fmaf(a1[cc], b1.y, acc[1][5]);
                    acc[1][6] = fmaf(a1[cc], b1.z, acc[1][6]);
                    acc[1][7] = fmaf(a1[cc], b1.w, acc[1][7]);
                    acc[2][0] = fmaf(a2[cc], b0.x, acc[2][0]);
                    acc[2][1] = fmaf(a2[cc], b0.y, acc[2][1]);
                    acc[2][2] = fmaf(a2[cc], b0.z, acc[2][2]);
                    acc[2][3] = fmaf(a2[cc], b0.w, acc[2][3]);
                    acc[2][4] = fmaf(a2[cc], b1.x, acc[2][4]);
                    acc[2][5] = fmaf(a2[cc], b1.y, acc[2][5]);
                    acc[2][6] = fmaf(a2[cc], b1.z, acc[2][6]);
                    acc[2][7] = fmaf(a2[cc], b1.w, acc[2][7]);
                    acc[3][0] = fmaf(a3[cc], b0.x, acc[3][0]);
                    acc[3][1] = fmaf(a3[cc], b0.y, acc[3][1]);
                    acc[3][2] = fmaf(a3[cc], b0.z, acc[3][2]);
                    acc[3][3] = fmaf(a3[cc], b0.w, acc[3][3]);
                    acc[3][4] = fmaf(a3[cc], b1.x, acc[3][4]);
                    acc[3][5] = fmaf(a3[cc], b1.y, acc[3][5]);
                    acc[3][6] = fmaf(a3[cc], b1.z, acc[3][6]);
                    acc[3][7] = fmaf(a3[cc], b1.w, acc[3][7]);
                }
            }
        }
    }

    // ---- epilogue: score = psq + csq - 2*dot ; out = exp(-beta*score) ----
    const int oh = oh0 + prow;
    if (oh < HoN) {
        const int f0 = fid * 4;
        const float cs0 = csq[f0 + 0],  cs1 = csq[f0 + 1];
        const float cs2 = csq[f0 + 2],  cs3 = csq[f0 + 3];
        const float cs4 = csq[f0 + 32], cs5 = csq[f0 + 33];
        const float cs6 = csq[f0 + 34], cs7 = csq[f0 + 35];
        const float bt0 = sbeta[f0 + 0],  bt1 = sbeta[f0 + 1];
        const float bt2 = sbeta[f0 + 2],  bt3 = sbeta[f0 + 3];
        const float bt4 = sbeta[f0 + 32], bt5 = sbeta[f0 + 33];
        const float bt6 = sbeta[f0 + 34], bt7 = sbeta[f0 + 35];

        #pragma unroll
        for (int px = 0; px < 4; ++px) {
            const int ow = ow0 + pcg * 4 + px;
            if (ow < WoN) {
                const float ps = psq[prow * TILE_W + pcg * 4 + px];
                float4 r0, r1;
                r0.x = __expf(-bt0 * (ps + cs0 - 2.f * acc[px][0]));
                r0.y = __expf(-bt1 * (ps + cs1 - 2.f * acc[px][1]));
                r0.z = __expf(-bt2 * (ps + cs2 - 2.f * acc[px][2]));
                r0.w = __expf(-bt3 * (ps + cs3 - 2.f * acc[px][3]));
                r1.x = __expf(-bt4 * (ps + cs4 - 2.f * acc[px][4]));
                r1.y = __expf(-bt5 * (ps + cs5 - 2.f * acc[px][5]));
                r1.z = __expf(-bt6 * (ps + cs6 - 2.f * acc[px][6]));
                r1.w = __expf(-bt7 * (ps + cs7 - 2.f * acc[px][7]));
                float* op = out + (((size_t)b * HoN + oh) * WoN + ow) * Fn
                                + fh * FHALF + f0;
                *reinterpret_cast<float4*>(op)      = r0;
                *reinterpret_cast<float4*>(op + 32) = r1;
            }
        }
    }
}

extern "C" void kernel_launch(void* const* d_in, const int* in_sizes, int n_in,
                              void* d_out, int out_size)
{
    (void)in_sizes; (void)n_in; (void)out_size;
    const float* x    = (const float*)d_in[0];
    const float* ccs  = (const float*)d_in[1];
    const float* beta = (const float*)d_in[2];
    float* out = (float*)d_out;

    // Opt-in to >48KB dynamic smem (idempotent, not a stream op -> capture-safe).
    cudaFuncSetAttribute(rbfolution_kernel,
                         cudaFuncAttributeMaxDynamicSharedMemorySize, SMEM_BYTES);

    dim3 grid((WoN + TILE_W - 1) / TILE_W,   // 14
              (HoN + TILE_H - 1) / TILE_H,   // 7
              Bn * 2);                       // 32 batches x 2 filter halves
    rbfolution_kernel<<<grid, THREADS, SMEM_BYTES>>>(x, ccs, beta, out);
}